// round 1
// baseline (speedup 1.0000x reference)
#include <cuda_runtime.h>
#include <math.h>

#define B_   128
#define S_   179
#define E_   1024
#define H_   16
#define D_   64
#define BS_  (B_ * S_)          // 22912 (= 179 * 128, exact)
#define BHSD (B_ * H_ * S_ * D_)

// Scratch (allocation-free): Q/K/V in [B,H,S,D], attention output in [B,S,E]
__device__ float g_Q[BHSD];
__device__ float g_K[BHSD];
__device__ float g_V[BHSD];
__device__ float g_att[BS_ * E_];

// ---------------------------------------------------------------------------
// Kernel 1: QKV projection.  C = A @ W^T  (A=[M,K] row-major, W=[N,K] row-major)
// Classic 128x128x8 SGEMM, 256 threads, 8x8 per thread. Output scattered into
// [B,H,S,D] layout so the attention kernel reads contiguous per-(b,h) tiles.
// Grid: (179 M-tiles, 8 N-tiles, 3 matrices)
// ---------------------------------------------------------------------------
__global__ __launch_bounds__(256) void qkv_gemm(
    const float* __restrict__ A,
    const float* __restrict__ W0,
    const float* __restrict__ W1,
    const float* __restrict__ W2)
{
    __shared__ float As[8][128];
    __shared__ float Bs[8][128];

    const int z = blockIdx.z;
    const float* __restrict__ Wt = (z == 0) ? W0 : ((z == 1) ? W1 : W2);
    float* __restrict__ Out = (z == 0) ? g_Q : ((z == 1) ? g_K : g_V);

    const int bm  = blockIdx.x * 128;
    const int bn  = blockIdx.y * 128;
    const int tid = threadIdx.x;

    // loader mapping: 256 threads, each one float4 of the 128x8 tile
    const int lrow = tid >> 1;          // 0..127
    const int lk   = (tid & 1) * 4;     // 0 or 4
    // compute mapping: 16x16 threads, each 8x8
    const int ty = tid >> 4;
    const int tx = tid & 15;

    const float* Aptr = A  + (size_t)(bm + lrow) * E_ + lk;
    const float* Bptr = Wt + (size_t)(bn + lrow) * E_ + lk;

    float acc[8][8];
#pragma unroll
    for (int i = 0; i < 8; i++)
#pragma unroll
        for (int j = 0; j < 8; j++) acc[i][j] = 0.f;

    for (int k0 = 0; k0 < E_; k0 += 8) {
        float4 av = *(const float4*)(Aptr + k0);
        float4 bv = *(const float4*)(Bptr + k0);
        __syncthreads();
        As[lk + 0][lrow] = av.x; As[lk + 1][lrow] = av.y;
        As[lk + 2][lrow] = av.z; As[lk + 3][lrow] = av.w;
        Bs[lk + 0][lrow] = bv.x; Bs[lk + 1][lrow] = bv.y;
        Bs[lk + 2][lrow] = bv.z; Bs[lk + 3][lrow] = bv.w;
        __syncthreads();
#pragma unroll
        for (int kk = 0; kk < 8; kk++) {
            float4 a0 = *(const float4*)&As[kk][ty * 8];
            float4 a1 = *(const float4*)&As[kk][ty * 8 + 4];
            float4 b0 = *(const float4*)&Bs[kk][tx * 8];
            float4 b1 = *(const float4*)&Bs[kk][tx * 8 + 4];
            float a[8] = {a0.x, a0.y, a0.z, a0.w, a1.x, a1.y, a1.z, a1.w};
            float b[8] = {b0.x, b0.y, b0.z, b0.w, b1.x, b1.y, b1.z, b1.w};
#pragma unroll
            for (int i = 0; i < 8; i++)
#pragma unroll
                for (int j = 0; j < 8; j++)
                    acc[i][j] = fmaf(a[i], b[j], acc[i][j]);
        }
    }

    // scatter to [B,H,S,D]; the 8-wide j-run never crosses a 64 boundary
    const int n0 = bn + tx * 8;
    const int h  = n0 >> 6;
    const int d0 = n0 & 63;
#pragma unroll
    for (int i = 0; i < 8; i++) {
        int m  = bm + ty * 8 + i;
        int bb = m / S_;
        int ss = m - bb * S_;
        float* dst = Out + (((size_t)(bb * H_ + h) * S_ + ss) * D_ + d0);
        *(float4*)(dst)     = make_float4(acc[i][0], acc[i][1], acc[i][2], acc[i][3]);
        *(float4*)(dst + 4) = make_float4(acc[i][4], acc[i][5], acc[i][6], acc[i][7]);
    }
}

// ---------------------------------------------------------------------------
// Kernel 2: attention for one (b,h).  Q,K,V staged in smem (pitch 65 to avoid
// 32-way bank conflicts on the stride-64 column reads). One warp per query row:
// each lane owns keys {lane, lane+32, ...} (6 regs of logits), warp-reduce
// max/sum, then PV with shfl-broadcast probabilities.
// Grid: 2048 blocks (B*H), 256 threads. Dynamic smem 3*179*65*4 = 139,620 B.
// ---------------------------------------------------------------------------
__global__ __launch_bounds__(256) void attn_kernel()
{
    extern __shared__ float sm[];
    float* sQ = sm;
    float* sK = sm + S_ * 65;
    float* sV = sm + 2 * S_ * 65;

    const int bh = blockIdx.x;            // b*16 + h
    const int b  = bh >> 4;
    const int h  = bh & 15;
    const float* __restrict__ Qg = g_Q + (size_t)bh * (S_ * D_);
    const float* __restrict__ Kg = g_K + (size_t)bh * (S_ * D_);
    const float* __restrict__ Vg = g_V + (size_t)bh * (S_ * D_);

    const int tid = threadIdx.x;
    for (int i = tid; i < S_ * D_; i += 256) {
        int r = i >> 6, c = i & 63;
        sQ[r * 65 + c] = Qg[i];
        sK[r * 65 + c] = Kg[i];
        sV[r * 65 + c] = Vg[i];
    }
    __syncthreads();

    const int wid  = tid >> 5;
    const int lane = tid & 31;
    const float wsc = 0.03125f / 179.0f;   // E^-0.5 / N

    for (int q = wid; q < S_; q += 8) {
        float p[6];
        float mx = -1e30f;
#pragma unroll
        for (int t = 0; t < 6; t++) {
            int k = t * 32 + lane;
            float lg = -1e30f;
            if (k < S_) {
                float dot = 0.f;
                const float* qr = sQ + q * 65;
                const float* kr = sK + k * 65;
#pragma unroll
                for (int d = 0; d < 64; d++) dot = fmaf(qr[d], kr[d], dot);
                lg = dot * wsc * fabsf((float)(q - k));
            }
            p[t] = lg;
            mx = fmaxf(mx, lg);
        }
#pragma unroll
        for (int o = 16; o > 0; o >>= 1) mx = fmaxf(mx, __shfl_xor_sync(0xffffffffu, mx, o));
        float sum = 0.f;
#pragma unroll
        for (int t = 0; t < 6; t++) {
            float e = (t * 32 + lane < S_) ? __expf(p[t] - mx) : 0.f;
            p[t] = e;
            sum += e;
        }
#pragma unroll
        for (int o = 16; o > 0; o >>= 1) sum += __shfl_xor_sync(0xffffffffu, sum, o);
        const float inv = 1.0f / sum;

        float a0 = 0.f, a1 = 0.f;
#pragma unroll
        for (int t = 0; t < 6; t++) {
#pragma unroll
            for (int j = 0; j < 32; j++) {
                int k = t * 32 + j;
                if (k >= S_) break;     // compile-time per (t,j)
                float pk = __shfl_sync(0xffffffffu, p[t], j);
                a0 = fmaf(pk, sV[k * 65 + lane], a0);
                a1 = fmaf(pk, sV[k * 65 + 32 + lane], a1);
            }
        }
        float* o = g_att + ((size_t)(b * S_ + q)) * E_ + h * 64;
        o[lane]      = a0 * inv;
        o[lane + 32] = a1 * inv;
    }
}

// ---------------------------------------------------------------------------
// Kernel 3: LayerNorm over last dim (1024). One block per row, float4 path.
// ---------------------------------------------------------------------------
__global__ __launch_bounds__(256) void ln_kernel(
    const float* __restrict__ gamma,
    const float* __restrict__ beta,
    float* __restrict__ out)
{
    const int row = blockIdx.x;
    const int tid = threadIdx.x;
    const float4 v = ((const float4*)(g_att + (size_t)row * E_))[tid];

    float s  = v.x + v.y + v.z + v.w;
    float s2 = v.x * v.x + v.y * v.y + v.z * v.z + v.w * v.w;
#pragma unroll
    for (int o = 16; o > 0; o >>= 1) {
        s  += __shfl_xor_sync(0xffffffffu, s, o);
        s2 += __shfl_xor_sync(0xffffffffu, s2, o);
    }
    __shared__ float red[2][8];
    const int wid = tid >> 5, lane = tid & 31;
    if (lane == 0) { red[0][wid] = s; red[1][wid] = s2; }
    __syncthreads();
    float fs = 0.f, fs2 = 0.f;
#pragma unroll
    for (int w = 0; w < 8; w++) { fs += red[0][w]; fs2 += red[1][w]; }

    const float mu  = fs * (1.0f / E_);
    const float var = fs2 * (1.0f / E_) - mu * mu;
    const float inv = rsqrtf(var + 1e-5f);

    const float4 g  = ((const float4*)gamma)[tid];
    const float4 bt = ((const float4*)beta)[tid];
    float4 r;
    r.x = (v.x - mu) * inv * g.x + bt.x;
    r.y = (v.y - mu) * inv * g.y + bt.y;
    r.z = (v.z - mu) * inv * g.z + bt.z;
    r.w = (v.w - mu) * inv * g.w + bt.w;
    ((float4*)out)[(size_t)row * 256 + tid] = r;
}

// ---------------------------------------------------------------------------
extern "C" void kernel_launch(void* const* d_in, const int* in_sizes, int n_in,
                              void* d_out, int out_size)
{
    const float* x     = (const float*)d_in[0];
    const float* Wq    = (const float*)d_in[1];
    const float* Wk    = (const float*)d_in[2];
    const float* Wv    = (const float*)d_in[3];
    const float* gamma = (const float*)d_in[4];
    const float* beta  = (const float*)d_in[5];
    float* out = (float*)d_out;

    const int attn_smem = 3 * S_ * 65 * (int)sizeof(float); // 139,620 B
    cudaFuncSetAttribute(attn_kernel, cudaFuncAttributeMaxDynamicSharedMemorySize, attn_smem);

    qkv_gemm<<<dim3(BS_ / 128, E_ / 128, 3), 256>>>(x, Wq, Wk, Wv);
    attn_kernel<<<B_ * H_, 256, attn_smem>>>();
    ln_kernel<<<BS_, 256>>>(gamma, beta, out);
}

// round 3
// speedup vs baseline: 1.5281x; 1.5281x over previous
#include <cuda_runtime.h>
#include <cuda_bf16.h>
#include <cstdint>
#include <math.h>

#define B_   128
#define S_   179
#define E_   1024
#define H_   16
#define D_   64
#define BS_  (B_ * S_)          // 22912
#define BHSD (B_ * H_ * S_ * D_)

__device__ float g_Q[BHSD];
__device__ float g_K[BHSD];
__device__ float g_V[BHSD];
__device__ float g_att[BS_ * E_];

// ---------------------------------------------------------------------------
// helpers
// ---------------------------------------------------------------------------
__device__ __forceinline__ uint32_t smem_u32(const void* p) {
    uint32_t a;
    asm("{ .reg .u64 t; cvta.to.shared.u64 t, %1; cvt.u32.u64 %0, t; }" : "=r"(a) : "l"(p));
    return a;
}
__device__ __forceinline__ uint32_t pack_bf16(float x, float y) {
    __nv_bfloat162 h = __floats2bfloat162_rn(x, y);
    return *reinterpret_cast<uint32_t*>(&h);
}
// hi/lo split of a float pair -> (hi packed, lo packed)
__device__ __forceinline__ void split2(float x, float y, uint32_t& hi, uint32_t& lo) {
    __nv_bfloat16 hx = __float2bfloat16(x);
    __nv_bfloat16 hy = __float2bfloat16(y);
    float rx = x - __bfloat162float(hx);
    float ry = y - __bfloat162float(hy);
    __nv_bfloat162 hp; hp.x = hx; hp.y = hy;
    hi = *reinterpret_cast<uint32_t*>(&hp);
    lo = pack_bf16(rx, ry);
}

#define LDSM_X4(r0, r1, r2, r3, addr)                                          \
    asm volatile("ldmatrix.sync.aligned.m8n8.x4.shared.b16 {%0,%1,%2,%3}, [%4];" \
                 : "=r"(r0), "=r"(r1), "=r"(r2), "=r"(r3) : "r"(addr))

#define MMA_BF16(c, a0, a1, a2, a3, b0, b1)                                    \
    asm volatile("mma.sync.aligned.m16n8k16.row.col.f32.bf16.bf16.f32 "        \
        "{%0,%1,%2,%3}, {%4,%5,%6,%7}, {%8,%9}, {%0,%1,%2,%3};"                \
        : "+f"((c)[0]), "+f"((c)[1]), "+f"((c)[2]), "+f"((c)[3])               \
        : "r"(a0), "r"(a1), "r"(a2), "r"(a3), "r"(b0), "r"(b1))

// ---------------------------------------------------------------------------
// Kernel 1: QKV projection, bf16 split-MMA.  C = A @ W^T (both K-major).
// 128x128 tile, KC=32, double-buffered smem.
// Smem row: 64 bf16 (hi cols 0-31, lo cols 32-63), pitch 144 B (conflict-free).
// 8 warps: 2 (M, 64 rows) x 4 (N, 32 cols). Per warp: 4 mtiles x 4 ntiles.
// ---------------------------------------------------------------------------
#define KC      32
#define NCHUNK  (E_ / KC)       // 32
#define PITCH   144
#define TILE_B  (128 * PITCH)   // 18432
#define STG_B   (2 * TILE_B)    // A + B = 36864

__global__ __launch_bounds__(256) void qkv_gemm_tc(
    const float* __restrict__ A,
    const float* __restrict__ W0,
    const float* __restrict__ W1,
    const float* __restrict__ W2)
{
    extern __shared__ __align__(128) char sb[];

    const int z = blockIdx.z;
    const float* __restrict__ Wt = (z == 0) ? W0 : ((z == 1) ? W1 : W2);
    float* __restrict__ Out = (z == 0) ? g_Q : ((z == 1) ? g_K : g_V);

    const int bm  = blockIdx.x * 128;
    const int bn  = blockIdx.y * 128;
    const int tid = threadIdx.x;
    const int wid = tid >> 5;
    const int lane = tid & 31;

    const uint32_t sbase = smem_u32(sb);

    // ---- loader mapping: thread t -> row t>>1, 16 floats from (t&1)*16
    const int lr = tid >> 1;
    const int lc = (tid & 1) * 16;
    const float* ga = A  + (size_t)(bm + lr) * E_ + lc;
    const float* gb = Wt + (size_t)(bn + lr) * E_ + lc;
    const uint32_t srowA = (uint32_t)lr * PITCH + (uint32_t)lc * 2;          // hi bytes
    const uint32_t srowB = TILE_B + (uint32_t)lr * PITCH + (uint32_t)lc * 2;

    // ---- warp compute mapping
    const int warp_m = (wid >> 2) * 64;
    const int warp_n = (wid & 3) * 32;
    // ldmatrix A: lane -> row (lane&15), kofs (lane>>4)*8
    const uint32_t aRow = (uint32_t)(warp_m + (lane & 15));
    const uint32_t aKof = (uint32_t)((lane >> 4) * 8);
    // ldmatrix B: lane -> n row, kofs
    const uint32_t bRow = (uint32_t)(warp_n + ((lane >> 4) << 3) + (lane & 7));
    const uint32_t bKof = (uint32_t)(((lane >> 3) & 1) * 8);

    float acc[4][4][4];
#pragma unroll
    for (int i = 0; i < 4; i++)
#pragma unroll
        for (int j = 0; j < 4; j++)
#pragma unroll
            for (int k = 0; k < 4; k++) acc[i][j][k] = 0.f;

    // ---- prologue: chunk 0 -> stage 0
    {
        char* dst = sb;
#pragma unroll
        for (int j = 0; j < 4; j++) {
            float4 av = *(const float4*)(ga + j * 4);
            float4 bv = *(const float4*)(gb + j * 4);
            uint32_t h0, l0, h1, l1;
            split2(av.x, av.y, h0, l0); split2(av.z, av.w, h1, l1);
            *(uint2*)(dst + srowA + j * 8)      = make_uint2(h0, h1);
            *(uint2*)(dst + srowA + 64 + j * 8) = make_uint2(l0, l1);
            split2(bv.x, bv.y, h0, l0); split2(bv.z, bv.w, h1, l1);
            *(uint2*)(dst + srowB + j * 8)      = make_uint2(h0, h1);
            *(uint2*)(dst + srowB + 64 + j * 8) = make_uint2(l0, l1);
        }
    }
    __syncthreads();

    for (int c = 0; c < NCHUNK; c++) {
        // prefetch next chunk's globals into registers
        float4 av[4], bv[4];
        if (c + 1 < NCHUNK) {
            const float* pa = ga + (c + 1) * KC;
            const float* pb = gb + (c + 1) * KC;
#pragma unroll
            for (int j = 0; j < 4; j++) { av[j] = *(const float4*)(pa + j * 4);
                                          bv[j] = *(const float4*)(pb + j * 4); }
        }

        // ---- compute on stage c&1
        const uint32_t stA = sbase + (uint32_t)(c & 1) * STG_B;
        const uint32_t stB = stA + TILE_B;
#pragma unroll
        for (int kk = 0; kk < KC; kk += 16) {
            uint32_t Ah[4][4], Al[4][4];
#pragma unroll
            for (int mt = 0; mt < 4; mt++) {
                uint32_t ad = stA + (aRow + mt * 16) * PITCH + (kk + aKof) * 2;
                LDSM_X4(Ah[mt][0], Ah[mt][1], Ah[mt][2], Ah[mt][3], ad);
                LDSM_X4(Al[mt][0], Al[mt][1], Al[mt][2], Al[mt][3], ad + 64);
            }
            uint32_t Bh[4][2], Bl[4][2];
#pragma unroll
            for (int np = 0; np < 2; np++) {
                uint32_t bd = stB + (bRow + np * 16) * PITCH + (kk + bKof) * 2;
                LDSM_X4(Bh[np*2][0], Bh[np*2][1], Bh[np*2+1][0], Bh[np*2+1][1], bd);
                LDSM_X4(Bl[np*2][0], Bl[np*2][1], Bl[np*2+1][0], Bl[np*2+1][1], bd + 64);
            }
#pragma unroll
            for (int mt = 0; mt < 4; mt++)
#pragma unroll
                for (int nt = 0; nt < 4; nt++) {
                    MMA_BF16(acc[mt][nt], Ah[mt][0], Ah[mt][1], Ah[mt][2], Ah[mt][3],
                             Bh[nt][0], Bh[nt][1]);
                    MMA_BF16(acc[mt][nt], Ah[mt][0], Ah[mt][1], Ah[mt][2], Ah[mt][3],
                             Bl[nt][0], Bl[nt][1]);
                    MMA_BF16(acc[mt][nt], Al[mt][0], Al[mt][1], Al[mt][2], Al[mt][3],
                             Bh[nt][0], Bh[nt][1]);
                }
        }

        // ---- store prefetched chunk into the other stage
        if (c + 1 < NCHUNK) {
            char* dst = sb + ((c + 1) & 1) * STG_B;
#pragma unroll
            for (int j = 0; j < 4; j++) {
                uint32_t h0, l0, h1, l1;
                split2(av[j].x, av[j].y, h0, l0); split2(av[j].z, av[j].w, h1, l1);
                *(uint2*)(dst + srowA + j * 8)      = make_uint2(h0, h1);
                *(uint2*)(dst + srowA + 64 + j * 8) = make_uint2(l0, l1);
                split2(bv[j].x, bv[j].y, h0, l0); split2(bv[j].z, bv[j].w, h1, l1);
                *(uint2*)(dst + srowB + j * 8)      = make_uint2(h0, h1);
                *(uint2*)(dst + srowB + 64 + j * 8) = make_uint2(l0, l1);
            }
        }
        __syncthreads();
    }

    // ---- epilogue: scatter accumulators to [B,H,S,D]
#pragma unroll
    for (int mt = 0; mt < 4; mt++) {
        const int r0 = bm + warp_m + mt * 16 + (lane >> 2);
        const int r1 = r0 + 8;
        const int bb0 = r0 / S_, ss0 = r0 - bb0 * S_;
        const int bb1 = r1 / S_, ss1 = r1 - bb1 * S_;
#pragma unroll
        for (int nt = 0; nt < 4; nt++) {
            const int n  = bn + warp_n + nt * 8 + ((lane & 3) * 2);
            const int h  = n >> 6;
            const int d  = n & 63;
            float* p0 = Out + (((size_t)(bb0 * H_ + h) * S_ + ss0) * D_ + d);
            float* p1 = Out + (((size_t)(bb1 * H_ + h) * S_ + ss1) * D_ + d);
            *(float2*)p0 = make_float2(acc[mt][nt][0], acc[mt][nt][1]);
            *(float2*)p1 = make_float2(acc[mt][nt][2], acc[mt][nt][3]);
        }
    }
}

// ---------------------------------------------------------------------------
// Kernel 2: attention (unchanged)
// ---------------------------------------------------------------------------
__global__ __launch_bounds__(256) void attn_kernel()
{
    extern __shared__ float sm[];
    float* sQ = sm;
    float* sK = sm + S_ * 65;
    float* sV = sm + 2 * S_ * 65;

    const int bh = blockIdx.x;
    const int b  = bh >> 4;
    const int h  = bh & 15;
    const float* __restrict__ Qg = g_Q + (size_t)bh * (S_ * D_);
    const float* __restrict__ Kg = g_K + (size_t)bh * (S_ * D_);
    const float* __restrict__ Vg = g_V + (size_t)bh * (S_ * D_);

    const int tid = threadIdx.x;
    for (int i = tid; i < S_ * D_; i += 256) {
        int r = i >> 6, c = i & 63;
        sQ[r * 65 + c] = Qg[i];
        sK[r * 65 + c] = Kg[i];
        sV[r * 65 + c] = Vg[i];
    }
    __syncthreads();

    const int wid  = tid >> 5;
    const int lane = tid & 31;
    const float wsc = 0.03125f / 179.0f;

    for (int q = wid; q < S_; q += 8) {
        float p[6];
        float mx = -1e30f;
#pragma unroll
        for (int t = 0; t < 6; t++) {
            int k = t * 32 + lane;
            float lg = -1e30f;
            if (k < S_) {
                float dot = 0.f;
                const float* qr = sQ + q * 65;
                const float* kr = sK + k * 65;
#pragma unroll
                for (int d = 0; d < 64; d++) dot = fmaf(qr[d], kr[d], dot);
                lg = dot * wsc * fabsf((float)(q - k));
            }
            p[t] = lg;
            mx = fmaxf(mx, lg);
        }
#pragma unroll
        for (int o = 16; o > 0; o >>= 1) mx = fmaxf(mx, __shfl_xor_sync(0xffffffffu, mx, o));
        float sum = 0.f;
#pragma unroll
        for (int t = 0; t < 6; t++) {
            float e = (t * 32 + lane < S_) ? __expf(p[t] - mx) : 0.f;
            p[t] = e;
            sum += e;
        }
#pragma unroll
        for (int o = 16; o > 0; o >>= 1) sum += __shfl_xor_sync(0xffffffffu, sum, o);
        const float inv = 1.0f / sum;

        float a0 = 0.f, a1 = 0.f;
#pragma unroll
        for (int t = 0; t < 6; t++) {
#pragma unroll
            for (int j = 0; j < 32; j++) {
                int k = t * 32 + j;
                if (k >= S_) break;
                float pk = __shfl_sync(0xffffffffu, p[t], j);
                a0 = fmaf(pk, sV[k * 65 + lane], a0);
                a1 = fmaf(pk, sV[k * 65 + 32 + lane], a1);
            }
        }
        float* o = g_att + ((size_t)(b * S_ + q)) * E_ + h * 64;
        o[lane]      = a0 * inv;
        o[lane + 32] = a1 * inv;
    }
}

// ---------------------------------------------------------------------------
// Kernel 3: LayerNorm (unchanged)
// ---------------------------------------------------------------------------
__global__ __launch_bounds__(256) void ln_kernel(
    const float* __restrict__ gamma,
    const float* __restrict__ beta,
    float* __restrict__ out)
{
    const int row = blockIdx.x;
    const int tid = threadIdx.x;
    const float4 v = ((const float4*)(g_att + (size_t)row * E_))[tid];

    float s  = v.x + v.y + v.z + v.w;
    float s2 = v.x * v.x + v.y * v.y + v.z * v.z + v.w * v.w;
#pragma unroll
    for (int o = 16; o > 0; o >>= 1) {
        s  += __shfl_xor_sync(0xffffffffu, s, o);
        s2 += __shfl_xor_sync(0xffffffffu, s2, o);
    }
    __shared__ float red[2][8];
    const int wid = tid >> 5, lane = tid & 31;
    if (lane == 0) { red[0][wid] = s; red[1][wid] = s2; }
    __syncthreads();
    float fs = 0.f, fs2 = 0.f;
#pragma unroll
    for (int w = 0; w < 8; w++) { fs += red[0][w]; fs2 += red[1][w]; }

    const float mu  = fs * (1.0f / E_);
    const float var = fs2 * (1.0f / E_) - mu * mu;
    const float inv = rsqrtf(var + 1e-5f);

    const float4 g  = ((const float4*)gamma)[tid];
    const float4 bt = ((const float4*)beta)[tid];
    float4 r;
    r.x = (v.x - mu) * inv * g.x + bt.x;
    r.y = (v.y - mu) * inv * g.y + bt.y;
    r.z = (v.z - mu) * inv * g.z + bt.z;
    r.w = (v.w - mu) * inv * g.w + bt.w;
    ((float4*)out)[(size_t)row * 256 + tid] = r;
}

// ---------------------------------------------------------------------------
extern "C" void kernel_launch(void* const* d_in, const int* in_sizes, int n_in,
                              void* d_out, int out_size)
{
    const float* x     = (const float*)d_in[0];
    const float* Wq    = (const float*)d_in[1];
    const float* Wk    = (const float*)d_in[2];
    const float* Wv    = (const float*)d_in[3];
    const float* gamma = (const float*)d_in[4];
    const float* beta  = (const float*)d_in[5];
    float* out = (float*)d_out;

    const int gemm_smem = 2 * STG_B;                        // 73728
    cudaFuncSetAttribute(qkv_gemm_tc, cudaFuncAttributeMaxDynamicSharedMemorySize, gemm_smem);
    const int attn_smem = 3 * S_ * 65 * (int)sizeof(float); // 139620
    cudaFuncSetAttribute(attn_kernel, cudaFuncAttributeMaxDynamicSharedMemorySize, attn_smem);

    qkv_gemm_tc<<<dim3(BS_ / 128, E_ / 128, 3), 256, gemm_smem>>>(x, Wq, Wk, Wv);
    attn_kernel<<<B_ * H_, 256, attn_smem>>>();
    ln_kernel<<<BS_, 256>>>(gamma, beta, out);
}

// round 4
// speedup vs baseline: 3.0853x; 2.0191x over previous
#include <cuda_runtime.h>
#include <cuda_bf16.h>
#include <cstdint>
#include <math.h>

#define B_   128
#define S_   179
#define E_   1024
#define H_   16
#define D_   64
#define BS_  (B_ * S_)          // 22912
#define BH_  (B_ * H_)          // 2048
#define SP_  192                // padded sequence (12 x 16)

// GEMM outputs as bf16 hi/lo splits. Pad rows [179,192) are never written and
// stay zero (device globals are zero-initialized once; we only write s<179).
__device__ __nv_bfloat16 g_Qh[BH_ * SP_ * D_];
__device__ __nv_bfloat16 g_Ql[BH_ * SP_ * D_];
__device__ __nv_bfloat16 g_Kh[BH_ * SP_ * D_];
__device__ __nv_bfloat16 g_Kl[BH_ * SP_ * D_];
__device__ __nv_bfloat16 g_Vth[BH_ * D_ * SP_];   // transposed: [bh][d][s]
__device__ __nv_bfloat16 g_Vtl[BH_ * D_ * SP_];
__device__ float g_att[BS_ * E_];

// ---------------------------------------------------------------------------
// helpers
// ---------------------------------------------------------------------------
__device__ __forceinline__ uint32_t smem_u32(const void* p) {
    uint32_t a;
    asm("{ .reg .u64 t; cvta.to.shared.u64 t, %1; cvt.u32.u64 %0, t; }" : "=r"(a) : "l"(p));
    return a;
}
__device__ __forceinline__ uint32_t pack_bf16(float x, float y) {
    __nv_bfloat162 h = __floats2bfloat162_rn(x, y);
    return *reinterpret_cast<uint32_t*>(&h);
}
__device__ __forceinline__ void split2(float x, float y, uint32_t& hi, uint32_t& lo) {
    __nv_bfloat16 hx = __float2bfloat16(x);
    __nv_bfloat16 hy = __float2bfloat16(y);
    float rx = x - __bfloat162float(hx);
    float ry = y - __bfloat162float(hy);
    __nv_bfloat162 hp; hp.x = hx; hp.y = hy;
    hi = *reinterpret_cast<uint32_t*>(&hp);
    lo = pack_bf16(rx, ry);
}

#define LDSM_X4(r0, r1, r2, r3, addr)                                          \
    asm volatile("ldmatrix.sync.aligned.m8n8.x4.shared.b16 {%0,%1,%2,%3}, [%4];" \
                 : "=r"(r0), "=r"(r1), "=r"(r2), "=r"(r3) : "r"(addr))

#define MMA_BF16(c, a0, a1, a2, a3, b0, b1)                                    \
    asm volatile("mma.sync.aligned.m16n8k16.row.col.f32.bf16.bf16.f32 "        \
        "{%0,%1,%2,%3}, {%4,%5,%6,%7}, {%8,%9}, {%0,%1,%2,%3};"                \
        : "+f"((c)[0]), "+f"((c)[1]), "+f"((c)[2]), "+f"((c)[3])               \
        : "r"(a0), "r"(a1), "r"(a2), "r"(a3), "r"(b0), "r"(b1))

// ---------------------------------------------------------------------------
// Kernel 1: QKV projection, bf16 split-MMA.  C = A @ W^T (both K-major).
// 128-thread CTA, 4 warps (2x2 of 64x64), CTA tile 128x128, KC=16,
// double-buffered smem, pitch 80 B (conflict-free LDSM & STS), 2 CTAs/SM.
// Epilogue writes bf16 hi/lo into padded [BH,192,64] (Q,K) or transposed
// [BH,64,192] (V).
// ---------------------------------------------------------------------------
#define KC      16
#define NCHUNK  (E_ / KC)       // 64
#define PITCH_G 80
#define ATILE_G (128 * PITCH_G) // 10240
#define STAGE_G (2 * ATILE_G)   // 20480 (A + B)

__global__ __launch_bounds__(128, 2) void qkv_gemm_tc(
    const float* __restrict__ A,
    const float* __restrict__ W0,
    const float* __restrict__ W1,
    const float* __restrict__ W2)
{
    extern __shared__ __align__(128) char sb[];

    const int z = blockIdx.z;
    const float* __restrict__ Wt = (z == 0) ? W0 : ((z == 1) ? W1 : W2);

    const int bm  = blockIdx.x * 128;
    const int bn  = blockIdx.y * 128;
    const int tid = threadIdx.x;
    const int wid = tid >> 5;
    const int lane = tid & 31;

    const uint32_t sbase = smem_u32(sb);

    const int warp_m = (wid >> 1) * 64;
    const int warp_n = (wid & 1) * 64;

    // loader: thread t owns row t of both tiles (16 floats per chunk)
    const float* ga = A  + (size_t)(bm + tid) * E_;
    const float* gb = Wt + (size_t)(bn + tid) * E_;
    const uint32_t srow = (uint32_t)tid * PITCH_G;

    // ldmatrix lane addressing (round-3 verified conventions)
    const uint32_t aRow = (uint32_t)(lane & 15);
    const uint32_t aOff = (uint32_t)((lane >> 4) * 16);           // k-half bytes
    const uint32_t bRow = (uint32_t)(((lane >> 4) << 3) + (lane & 7));
    const uint32_t bOff = (uint32_t)(((lane >> 3) & 1) * 16);

    float acc[4][8][4];
#pragma unroll
    for (int i = 0; i < 4; i++)
#pragma unroll
        for (int j = 0; j < 8; j++)
#pragma unroll
            for (int k = 0; k < 4; k++) acc[i][j][k] = 0.f;

    // prologue: chunk 0 -> stage 0
    {
        char* dst = sb;
#pragma unroll
        for (int j = 0; j < 4; j++) {
            float4 av = *(const float4*)(ga + j * 4);
            float4 bv = *(const float4*)(gb + j * 4);
            uint32_t h0, l0, h1, l1;
            split2(av.x, av.y, h0, l0); split2(av.z, av.w, h1, l1);
            *(uint2*)(dst + srow + j * 8)      = make_uint2(h0, h1);
            *(uint2*)(dst + srow + 32 + j * 8) = make_uint2(l0, l1);
            split2(bv.x, bv.y, h0, l0); split2(bv.z, bv.w, h1, l1);
            *(uint2*)(dst + ATILE_G + srow + j * 8)      = make_uint2(h0, h1);
            *(uint2*)(dst + ATILE_G + srow + 32 + j * 8) = make_uint2(l0, l1);
        }
    }
    __syncthreads();

    for (int c = 0; c < NCHUNK; c++) {
        float4 av[2], bv[2], av2[2], bv2[2];
        if (c + 1 < NCHUNK) {
            const float* pa = ga + (c + 1) * KC;
            const float* pb = gb + (c + 1) * KC;
            av[0] = *(const float4*)(pa);      av[1] = *(const float4*)(pa + 4);
            av2[0] = *(const float4*)(pa + 8); av2[1] = *(const float4*)(pa + 12);
            bv[0] = *(const float4*)(pb);      bv[1] = *(const float4*)(pb + 4);
            bv2[0] = *(const float4*)(pb + 8); bv2[1] = *(const float4*)(pb + 12);
        }

        const uint32_t stA = sbase + (uint32_t)(c & 1) * STAGE_G;
        const uint32_t stB = stA + ATILE_G;

        uint32_t Ah[4][4], Al[4][4];
#pragma unroll
        for (int mt = 0; mt < 4; mt++) {
            uint32_t ad = stA + (uint32_t)(warp_m + mt * 16 + aRow) * PITCH_G + aOff;
            LDSM_X4(Ah[mt][0], Ah[mt][1], Ah[mt][2], Ah[mt][3], ad);
            LDSM_X4(Al[mt][0], Al[mt][1], Al[mt][2], Al[mt][3], ad + 32);
        }
#pragma unroll
        for (int np = 0; np < 4; np++) {
            uint32_t Bh[2][2], Bl[2][2];
            uint32_t bd = stB + (uint32_t)(warp_n + np * 16 + bRow) * PITCH_G + bOff;
            LDSM_X4(Bh[0][0], Bh[0][1], Bh[1][0], Bh[1][1], bd);
            LDSM_X4(Bl[0][0], Bl[0][1], Bl[1][0], Bl[1][1], bd + 32);
#pragma unroll
            for (int half = 0; half < 2; half++) {
                const int nt = np * 2 + half;
#pragma unroll
                for (int mt = 0; mt < 4; mt++) {
                    MMA_BF16(acc[mt][nt], Ah[mt][0], Ah[mt][1], Ah[mt][2], Ah[mt][3],
                             Bh[half][0], Bh[half][1]);
                    MMA_BF16(acc[mt][nt], Ah[mt][0], Ah[mt][1], Ah[mt][2], Ah[mt][3],
                             Bl[half][0], Bl[half][1]);
                    MMA_BF16(acc[mt][nt], Al[mt][0], Al[mt][1], Al[mt][2], Al[mt][3],
                             Bh[half][0], Bh[half][1]);
                }
            }
        }

        if (c + 1 < NCHUNK) {
            char* dst = sb + ((c + 1) & 1) * STAGE_G;
            uint32_t h0, l0, h1, l1;
            split2(av[0].x, av[0].y, h0, l0); split2(av[0].z, av[0].w, h1, l1);
            *(uint2*)(dst + srow)      = make_uint2(h0, h1);
            *(uint2*)(dst + srow + 32) = make_uint2(l0, l1);
            split2(av[1].x, av[1].y, h0, l0); split2(av[1].z, av[1].w, h1, l1);
            *(uint2*)(dst + srow + 8)      = make_uint2(h0, h1);
            *(uint2*)(dst + srow + 40) = make_uint2(l0, l1);
            split2(av2[0].x, av2[0].y, h0, l0); split2(av2[0].z, av2[0].w, h1, l1);
            *(uint2*)(dst + srow + 16)     = make_uint2(h0, h1);
            *(uint2*)(dst + srow + 48) = make_uint2(l0, l1);
            split2(av2[1].x, av2[1].y, h0, l0); split2(av2[1].z, av2[1].w, h1, l1);
            *(uint2*)(dst + srow + 24)     = make_uint2(h0, h1);
            *(uint2*)(dst + srow + 56) = make_uint2(l0, l1);

            char* db = dst + ATILE_G;
            split2(bv[0].x, bv[0].y, h0, l0); split2(bv[0].z, bv[0].w, h1, l1);
            *(uint2*)(db + srow)      = make_uint2(h0, h1);
            *(uint2*)(db + srow + 32) = make_uint2(l0, l1);
            split2(bv[1].x, bv[1].y, h0, l0); split2(bv[1].z, bv[1].w, h1, l1);
            *(uint2*)(db + srow + 8)      = make_uint2(h0, h1);
            *(uint2*)(db + srow + 40) = make_uint2(l0, l1);
            split2(bv2[0].x, bv2[0].y, h0, l0); split2(bv2[0].z, bv2[0].w, h1, l1);
            *(uint2*)(db + srow + 16)     = make_uint2(h0, h1);
            *(uint2*)(db + srow + 48) = make_uint2(l0, l1);
            split2(bv2[1].x, bv2[1].y, h0, l0); split2(bv2[1].z, bv2[1].w, h1, l1);
            *(uint2*)(db + srow + 24)     = make_uint2(h0, h1);
            *(uint2*)(db + srow + 56) = make_uint2(l0, l1);
        }
        __syncthreads();
    }

    // epilogue: hi/lo bf16 writes
#pragma unroll
    for (int mt = 0; mt < 4; mt++) {
        const int r0 = bm + warp_m + mt * 16 + (lane >> 2);
        const int r1 = r0 + 8;
        const int bb0 = r0 / S_, ss0 = r0 - bb0 * S_;
        const int bb1 = r1 / S_, ss1 = r1 - bb1 * S_;
#pragma unroll
        for (int nt = 0; nt < 8; nt++) {
            const int n  = warp_n + nt * 8 + ((lane & 3) * 2);
            const int h  = (bn + n) >> 6;
            const int d  = (bn + n) & 63;
            uint32_t hi0, lo0, hi1, lo1;
            split2(acc[mt][nt][0], acc[mt][nt][1], hi0, lo0);
            split2(acc[mt][nt][2], acc[mt][nt][3], hi1, lo1);
            if (z < 2) {
                __nv_bfloat16* Oh = (z == 0) ? g_Qh : g_Kh;
                __nv_bfloat16* Ol = (z == 0) ? g_Ql : g_Kl;
                size_t i0 = ((size_t)(bb0 * H_ + h) * SP_ + ss0) * D_ + d;
                size_t i1 = ((size_t)(bb1 * H_ + h) * SP_ + ss1) * D_ + d;
                *(uint32_t*)(Oh + i0) = hi0;  *(uint32_t*)(Ol + i0) = lo0;
                *(uint32_t*)(Oh + i1) = hi1;  *(uint32_t*)(Ol + i1) = lo1;
            } else {
                // V transposed: [bh][d][s]
                size_t base0 = ((size_t)(bb0 * H_ + h) * D_ + d) * SP_ + ss0;
                size_t base1 = ((size_t)(bb1 * H_ + h) * D_ + d) * SP_ + ss1;
                __nv_bfloat162 h2, l2;
                *(uint32_t*)&h2 = hi0; *(uint32_t*)&l2 = lo0;
                g_Vth[base0] = h2.x; g_Vth[base0 + SP_] = h2.y;
                g_Vtl[base0] = l2.x; g_Vtl[base0 + SP_] = l2.y;
                *(uint32_t*)&h2 = hi1; *(uint32_t*)&l2 = lo1;
                g_Vth[base1] = h2.x; g_Vth[base1 + SP_] = h2.y;
                g_Vtl[base1] = l2.x; g_Vtl[base1 + SP_] = l2.y;
            }
        }
    }
}

// ---------------------------------------------------------------------------
// Kernel 2: attention via bf16 split MMA. One block per (b,h), 256 threads.
// smem: Q,K [192 rows][64 hi | 64 lo] pitch 272; Vt [64 rows][192 hi | 192 lo]
// pitch 784 (both conflict-free for ldmatrix). Each warp owns 16-query mtiles.
// QK^T (3-product) -> bias+mask -> softmax in C-fragments -> P hi/lo split in
// register (C layout == A layout) -> PV (3-product) -> scaled store.
// ---------------------------------------------------------------------------
#define QKP   272
#define VTP   784
#define SQ_B  (SP_ * QKP)       // 52224
#define SVT_B (D_ * VTP)        // 50176
#define ATT_SMEM (2 * SQ_B + SVT_B)   // 154624

__global__ __launch_bounds__(256) void attn_kernel()
{
    extern __shared__ __align__(128) char sm[];
    char* sQ = sm;
    char* sK = sm + SQ_B;
    char* sV = sm + 2 * SQ_B;

    const int bh = blockIdx.x;
    const int b  = bh >> 4;
    const int h  = bh & 15;
    const int tid = threadIdx.x;
    const int wid = tid >> 5;
    const int lane = tid & 31;

    // ---- stage Q, K (hi+lo), Vt (hi+lo) into smem
    {
        const uint4* qh = (const uint4*)(g_Qh + (size_t)bh * SP_ * D_);
        const uint4* ql = (const uint4*)(g_Ql + (size_t)bh * SP_ * D_);
        const uint4* kh = (const uint4*)(g_Kh + (size_t)bh * SP_ * D_);
        const uint4* kl = (const uint4*)(g_Kl + (size_t)bh * SP_ * D_);
        for (int i = tid; i < SP_ * 8; i += 256) {
            int row = i >> 3, seg = i & 7;
            *(uint4*)(sQ + row * QKP + seg * 16)       = qh[i];
            *(uint4*)(sQ + row * QKP + 128 + seg * 16) = ql[i];
            *(uint4*)(sK + row * QKP + seg * 16)       = kh[i];
            *(uint4*)(sK + row * QKP + 128 + seg * 16) = kl[i];
        }
        const uint4* vh = (const uint4*)(g_Vth + (size_t)bh * D_ * SP_);
        const uint4* vl = (const uint4*)(g_Vtl + (size_t)bh * D_ * SP_);
        for (int i = tid; i < D_ * 24; i += 256) {
            int row = i / 24, seg = i - row * 24;
            *(uint4*)(sV + row * VTP + seg * 16)       = vh[i];
            *(uint4*)(sV + row * VTP + 384 + seg * 16) = vl[i];
        }
    }
    __syncthreads();

    const uint32_t sQb = smem_u32(sQ);
    const uint32_t sKb = smem_u32(sK);
    const uint32_t sVb = smem_u32(sV);

    const uint32_t aRow = (uint32_t)(lane & 15);
    const uint32_t aOff = (uint32_t)((lane >> 4) * 16);
    const uint32_t bRow = (uint32_t)(((lane >> 4) << 3) + (lane & 7));
    const uint32_t bOff = (uint32_t)(((lane >> 3) & 1) * 16);

    const float wsc = 0.03125f / 179.0f;   // E^-0.5 / N

    for (int mtl = wid; mtl < 12; mtl += 8) {
        // ---- QK^T: 16 rows x 192 keys
        float acc[24][4];
#pragma unroll
        for (int t = 0; t < 24; t++)
#pragma unroll
            for (int k = 0; k < 4; k++) acc[t][k] = 0.f;

#pragma unroll
        for (int s = 0; s < 4; s++) {
            uint32_t Ah[4], Al[4];
            uint32_t ad = sQb + (uint32_t)(mtl * 16 + aRow) * QKP + s * 32 + aOff;
            LDSM_X4(Ah[0], Ah[1], Ah[2], Ah[3], ad);
            LDSM_X4(Al[0], Al[1], Al[2], Al[3], ad + 128);
#pragma unroll
            for (int np = 0; np < 12; np++) {
                uint32_t Bh[2][2], Bl[2][2];
                uint32_t bd = sKb + (uint32_t)(np * 16 + bRow) * QKP + s * 32 + bOff;
                LDSM_X4(Bh[0][0], Bh[0][1], Bh[1][0], Bh[1][1], bd);
                LDSM_X4(Bl[0][0], Bl[0][1], Bl[1][0], Bl[1][1], bd + 128);
#pragma unroll
                for (int half = 0; half < 2; half++) {
                    const int nt = np * 2 + half;
                    MMA_BF16(acc[nt], Ah[0], Ah[1], Ah[2], Ah[3], Bh[half][0], Bh[half][1]);
                    MMA_BF16(acc[nt], Ah[0], Ah[1], Ah[2], Ah[3], Bl[half][0], Bl[half][1]);
                    MMA_BF16(acc[nt], Al[0], Al[1], Al[2], Al[3], Bh[half][0], Bh[half][1]);
                }
            }
        }

        // ---- bias + mask + softmax (rows r0 = c0/c1, r1 = c2/c3)
        const int q0 = mtl * 16 + (lane >> 2);
        const int q1 = q0 + 8;
        float m0 = -1e30f, m1 = -1e30f;
#pragma unroll
        for (int t = 0; t < 24; t++) {
            const int k0 = t * 8 + (lane & 3) * 2;
            const int k1 = k0 + 1;
            if (k0 < S_) {
                acc[t][0] *= wsc * fabsf((float)(q0 - k0));
                acc[t][2] *= wsc * fabsf((float)(q1 - k0));
            } else { acc[t][0] = -1e30f; acc[t][2] = -1e30f; }
            if (k1 < S_) {
                acc[t][1] *= wsc * fabsf((float)(q0 - k1));
                acc[t][3] *= wsc * fabsf((float)(q1 - k1));
            } else { acc[t][1] = -1e30f; acc[t][3] = -1e30f; }
            m0 = fmaxf(m0, fmaxf(acc[t][0], acc[t][1]));
            m1 = fmaxf(m1, fmaxf(acc[t][2], acc[t][3]));
        }
        m0 = fmaxf(m0, __shfl_xor_sync(0xffffffffu, m0, 1));
        m0 = fmaxf(m0, __shfl_xor_sync(0xffffffffu, m0, 2));
        m1 = fmaxf(m1, __shfl_xor_sync(0xffffffffu, m1, 1));
        m1 = fmaxf(m1, __shfl_xor_sync(0xffffffffu, m1, 2));

        float s0 = 0.f, s1 = 0.f;
#pragma unroll
        for (int t = 0; t < 24; t++) {
            acc[t][0] = __expf(acc[t][0] - m0);
            acc[t][1] = __expf(acc[t][1] - m0);
            acc[t][2] = __expf(acc[t][2] - m1);
            acc[t][3] = __expf(acc[t][3] - m1);
            s0 += acc[t][0] + acc[t][1];
            s1 += acc[t][2] + acc[t][3];
        }
        s0 += __shfl_xor_sync(0xffffffffu, s0, 1);
        s0 += __shfl_xor_sync(0xffffffffu, s0, 2);
        s1 += __shfl_xor_sync(0xffffffffu, s1, 1);
        s1 += __shfl_xor_sync(0xffffffffu, s1, 2);
        const float inv0 = 1.0f / s0;
        const float inv1 = 1.0f / s1;

        // ---- PV: P (registers, split) x Vt (smem) -> out 16 x 64
        float o[8][4];
#pragma unroll
        for (int nt = 0; nt < 8; nt++)
#pragma unroll
            for (int k = 0; k < 4; k++) o[nt][k] = 0.f;

#pragma unroll
        for (int s = 0; s < 12; s++) {
            // A frags from P: tiles 2s (k-low), 2s+1 (k-high)
            uint32_t h0, l0, h1, l1, h2, l2, h3, l3;
            split2(acc[2*s][0],   acc[2*s][1],   h0, l0);
            split2(acc[2*s][2],   acc[2*s][3],   h1, l1);
            split2(acc[2*s+1][0], acc[2*s+1][1], h2, l2);
            split2(acc[2*s+1][2], acc[2*s+1][3], h3, l3);
#pragma unroll
            for (int np = 0; np < 4; np++) {
                uint32_t Bh[2][2], Bl[2][2];
                uint32_t bd = sVb + (uint32_t)(np * 16 + bRow) * VTP + s * 32 + bOff;
                LDSM_X4(Bh[0][0], Bh[0][1], Bh[1][0], Bh[1][1], bd);
                LDSM_X4(Bl[0][0], Bl[0][1], Bl[1][0], Bl[1][1], bd + 384);
#pragma unroll
                for (int half = 0; half < 2; half++) {
                    const int nt = np * 2 + half;
                    MMA_BF16(o[nt], h0, h1, h2, h3, Bh[half][0], Bh[half][1]);
                    MMA_BF16(o[nt], h0, h1, h2, h3, Bl[half][0], Bl[half][1]);
                    MMA_BF16(o[nt], l0, l1, l2, l3, Bh[half][0], Bh[half][1]);
                }
            }
        }

        // ---- scaled store to g_att [b][s][h*64+d]
#pragma unroll
        for (int nt = 0; nt < 8; nt++) {
            const int d = nt * 8 + (lane & 3) * 2;
            if (q0 < S_) {
                float* p = g_att + ((size_t)(b * S_ + q0)) * E_ + h * 64 + d;
                *(float2*)p = make_float2(o[nt][0] * inv0, o[nt][1] * inv0);
            }
            if (q1 < S_) {
                float* p = g_att + ((size_t)(b * S_ + q1)) * E_ + h * 64 + d;
                *(float2*)p = make_float2(o[nt][2] * inv1, o[nt][3] * inv1);
            }
        }
    }
}

// ---------------------------------------------------------------------------
// Kernel 3: LayerNorm over last dim (1024). One block per row.
// ---------------------------------------------------------------------------
__global__ __launch_bounds__(256) void ln_kernel(
    const float* __restrict__ gamma,
    const float* __restrict__ beta,
    float* __restrict__ out)
{
    const int row = blockIdx.x;
    const int tid = threadIdx.x;
    const float4 v = ((const float4*)(g_att + (size_t)row * E_))[tid];

    float s  = v.x + v.y + v.z + v.w;
    float s2 = v.x * v.x + v.y * v.y + v.z * v.z + v.w * v.w;
#pragma unroll
    for (int o = 16; o > 0; o >>= 1) {
        s  += __shfl_xor_sync(0xffffffffu, s, o);
        s2 += __shfl_xor_sync(0xffffffffu, s2, o);
    }
    __shared__ float red[2][8];
    const int wid = tid >> 5, lane = tid & 31;
    if (lane == 0) { red[0][wid] = s; red[1][wid] = s2; }
    __syncthreads();
    float fs = 0.f, fs2 = 0.f;
#pragma unroll
    for (int w = 0; w < 8; w++) { fs += red[0][w]; fs2 += red[1][w]; }

    const float mu  = fs * (1.0f / E_);
    const float var = fs2 * (1.0f / E_) - mu * mu;
    const float inv = rsqrtf(var + 1e-5f);

    const float4 g  = ((const float4*)gamma)[tid];
    const float4 bt = ((const float4*)beta)[tid];
    float4 r;
    r.x = (v.x - mu) * inv * g.x + bt.x;
    r.y = (v.y - mu) * inv * g.y + bt.y;
    r.z = (v.z - mu) * inv * g.z + bt.z;
    r.w = (v.w - mu) * inv * g.w + bt.w;
    ((float4*)out)[(size_t)row * 256 + tid] = r;
}

// ---------------------------------------------------------------------------
extern "C" void kernel_launch(void* const* d_in, const int* in_sizes, int n_in,
                              void* d_out, int out_size)
{
    const float* x     = (const float*)d_in[0];
    const float* Wq    = (const float*)d_in[1];
    const float* Wk    = (const float*)d_in[2];
    const float* Wv    = (const float*)d_in[3];
    const float* gamma = (const float*)d_in[4];
    const float* beta  = (const float*)d_in[5];
    float* out = (float*)d_out;

    const int gemm_smem = 2 * STAGE_G;      // 40960
    cudaFuncSetAttribute(qkv_gemm_tc, cudaFuncAttributeMaxDynamicSharedMemorySize, gemm_smem);
    cudaFuncSetAttribute(attn_kernel, cudaFuncAttributeMaxDynamicSharedMemorySize, ATT_SMEM);

    qkv_gemm_tc<<<dim3(BS_ / 128, E_ / 128, 3), 128, gemm_smem>>>(x, Wq, Wk, Wv);
    attn_kernel<<<BH_, 256, ATT_SMEM>>>();
    ln_kernel<<<BS_, 256>>>(gamma, beta, out);
}

// round 5
// speedup vs baseline: 6.7839x; 2.1988x over previous
#include <cuda_runtime.h>
#include <cuda_fp16.h>
#include <cstdint>
#include <math.h>

#define B_   128
#define S_   179
#define E_   1024
#define H_   16
#define D_   64
#define BS_  (B_ * S_)          // 22912
#define BH_  (B_ * H_)          // 2048
#define SP_  192                // padded sequence (12 x 16)
#define EE_  (E_ * E_)

// fp16 copies of inputs: [ x (BS_*E_) | Wq | Wk | Wv ]
__device__ __half g_fp16[(size_t)BS_ * E_ + 3 * EE_];
// projection outputs (fp16). Pad rows [179,192) never written -> stay zero.
__device__ __half g_Qh[BH_ * SP_ * D_];
__device__ __half g_Kh[BH_ * SP_ * D_];
__device__ __half g_Vt[BH_ * D_ * SP_];   // transposed: [bh][d][s]
__device__ float g_att[(size_t)BS_ * E_];

// ---------------------------------------------------------------------------
// helpers
// ---------------------------------------------------------------------------
__device__ __forceinline__ uint32_t smem_u32(const void* p) {
    uint32_t a;
    asm("{ .reg .u64 t; cvta.to.shared.u64 t, %1; cvt.u32.u64 %0, t; }" : "=r"(a) : "l"(p));
    return a;
}
__device__ __forceinline__ uint32_t pack_h2(float x, float y) {
    __half2 h = __floats2half2_rn(x, y);
    return *reinterpret_cast<uint32_t*>(&h);
}

#define LDSM_X4(r0, r1, r2, r3, addr)                                          \
    asm volatile("ldmatrix.sync.aligned.m8n8.x4.shared.b16 {%0,%1,%2,%3}, [%4];" \
                 : "=r"(r0), "=r"(r1), "=r"(r2), "=r"(r3) : "r"(addr))

#define MMA_F16(c, a0, a1, a2, a3, b0, b1)                                     \
    asm volatile("mma.sync.aligned.m16n8k16.row.col.f32.f16.f16.f32 "          \
        "{%0,%1,%2,%3}, {%4,%5,%6,%7}, {%8,%9}, {%0,%1,%2,%3};"                \
        : "+f"((c)[0]), "+f"((c)[1]), "+f"((c)[2]), "+f"((c)[3])               \
        : "r"(a0), "r"(a1), "r"(a2), "r"(a3), "r"(b0), "r"(b1))

#define CP16(dst, src)                                                         \
    asm volatile("cp.async.cg.shared.global [%0], [%1], 16;" :: "r"(dst), "l"(src) : "memory")
#define CP_COMMIT()  asm volatile("cp.async.commit_group;" ::: "memory")
#define CP_WAIT2()   asm volatile("cp.async.wait_group 2;" ::: "memory")

// ---------------------------------------------------------------------------
// Kernel 0: fp32 -> fp16 pre-convert of x and the three weight matrices.
// ---------------------------------------------------------------------------
__global__ __launch_bounds__(256) void cvt_fp16(
    const float* __restrict__ x,  const float* __restrict__ Wq,
    const float* __restrict__ Wk, const float* __restrict__ Wv)
{
    const int z = blockIdx.y;
    const float* src = (z == 0) ? x : ((z == 1) ? Wq : ((z == 2) ? Wk : Wv));
    const size_t cnt = (z == 0) ? (size_t)BS_ * E_ : (size_t)EE_;
    const size_t off = (z == 0) ? 0 : (size_t)BS_ * E_ + (size_t)(z - 1) * EE_;
    const size_t i = ((size_t)blockIdx.x * 256 + threadIdx.x) * 4;
    if (i < cnt) {
        float4 v = *(const float4*)(src + i);
        *(uint2*)(g_fp16 + off + i) = make_uint2(pack_h2(v.x, v.y), pack_h2(v.z, v.w));
    }
}

// ---------------------------------------------------------------------------
// Kernel 1: QKV projection, single-product fp16 MMA.  C = A @ W^T.
// CTA 128x128, 4 warps (warp tile 64x64), KC=32, 4-stage cp.async pipeline,
// smem row pitch 80 B (conflict-free LDSM + cp.async stores).
// Epilogue: fp16 to padded [BH,192,64] (Q,K) or transposed [BH,64,192] (V).
// ---------------------------------------------------------------------------
#define KCH     32
#define NCH     (E_ / KCH)      // 32
#define PG      80
#define TILE_F  (128 * PG)      // 10240 per operand tile
#define STAGE_F (2 * TILE_F)    // 20480 (A+B)

__global__ __launch_bounds__(128, 2) void qkv_gemm_f16()
{
    extern __shared__ __align__(128) char sb[];
    const int z = blockIdx.z;
    const int bm = blockIdx.x * 128;
    const int bn = blockIdx.y * 128;
    const int tid = threadIdx.x;
    const int wid = tid >> 5;
    const int lane = tid & 31;

    const uint32_t sbase = smem_u32(sb);
    const int warp_m = (wid >> 1) * 64;
    const int warp_n = (wid & 1) * 64;

    const __half* gA = g_fp16 + (size_t)(bm + tid) * E_;
    const __half* gB = g_fp16 + (size_t)BS_ * E_ + (size_t)z * EE_ + (size_t)(bn + tid) * E_;
    const uint32_t dA0 = sbase + (uint32_t)tid * PG;

    // ldmatrix lane addressing (verified conventions)
    const uint32_t aRow = (uint32_t)(lane & 15);
    const uint32_t aOff = (uint32_t)((lane >> 4) * 16);
    const uint32_t bRow = (uint32_t)(((lane >> 4) << 3) + (lane & 7));
    const uint32_t bOff = (uint32_t)(((lane >> 3) & 1) * 16);

    float acc[4][8][4];
#pragma unroll
    for (int i = 0; i < 4; i++)
#pragma unroll
        for (int j = 0; j < 8; j++)
#pragma unroll
            for (int k = 0; k < 4; k++) acc[i][j][k] = 0.f;

    // prologue: issue chunks 0,1 into stages 0,1
#pragma unroll
    for (int p = 0; p < 2; p++) {
        uint32_t dA = dA0 + (uint32_t)p * STAGE_F;
        uint32_t dB = dA + TILE_F;
        const __half* sA = gA + p * KCH;
        const __half* sB = gB + p * KCH;
#pragma unroll
        for (int j = 0; j < 4; j++) {
            CP16(dA + j * 16, sA + j * 8);
            CP16(dB + j * 16, sB + j * 8);
        }
        CP_COMMIT();
    }

    for (int c = 0; c < NCH; c++) {
        if (c + 2 < NCH) {
            const int buf = (c + 2) & 3;
            uint32_t dA = dA0 + (uint32_t)buf * STAGE_F;
            uint32_t dB = dA + TILE_F;
            const __half* sA = gA + (c + 2) * KCH;
            const __half* sB = gB + (c + 2) * KCH;
#pragma unroll
            for (int j = 0; j < 4; j++) {
                CP16(dA + j * 16, sA + j * 8);
                CP16(dB + j * 16, sB + j * 8);
            }
        }
        CP_COMMIT();
        CP_WAIT2();
        __syncthreads();

        const uint32_t stA = sbase + (uint32_t)(c & 3) * STAGE_F;
        const uint32_t stB = stA + TILE_F;

        uint32_t Af[2][4][4];
#pragma unroll
        for (int s = 0; s < 2; s++)
#pragma unroll
            for (int mt = 0; mt < 4; mt++) {
                uint32_t ad = stA + (uint32_t)(warp_m + mt * 16 + aRow) * PG + s * 32 + aOff;
                LDSM_X4(Af[s][mt][0], Af[s][mt][1], Af[s][mt][2], Af[s][mt][3], ad);
            }
#pragma unroll
        for (int np = 0; np < 4; np++)
#pragma unroll
            for (int s = 0; s < 2; s++) {
                uint32_t B0, B1, B2, B3;
                uint32_t bd = stB + (uint32_t)(warp_n + np * 16 + bRow) * PG + s * 32 + bOff;
                LDSM_X4(B0, B1, B2, B3, bd);
#pragma unroll
                for (int mt = 0; mt < 4; mt++) {
                    MMA_F16(acc[mt][np * 2 + 0], Af[s][mt][0], Af[s][mt][1], Af[s][mt][2], Af[s][mt][3], B0, B1);
                    MMA_F16(acc[mt][np * 2 + 1], Af[s][mt][0], Af[s][mt][1], Af[s][mt][2], Af[s][mt][3], B2, B3);
                }
            }
    }

    // epilogue: fp16 stores
#pragma unroll
    for (int mt = 0; mt < 4; mt++) {
        const int r0 = bm + warp_m + mt * 16 + (lane >> 2);
        const int r1 = r0 + 8;
        const int bb0 = r0 / S_, ss0 = r0 - bb0 * S_;
        const int bb1 = r1 / S_, ss1 = r1 - bb1 * S_;
#pragma unroll
        for (int nt = 0; nt < 8; nt++) {
            const int n = bn + warp_n + nt * 8 + ((lane & 3) * 2);
            const int h = n >> 6;
            const int d = n & 63;
            if (z < 2) {
                __half* O = (z == 0) ? g_Qh : g_Kh;
                size_t i0 = ((size_t)(bb0 * H_ + h) * SP_ + ss0) * D_ + d;
                size_t i1 = ((size_t)(bb1 * H_ + h) * SP_ + ss1) * D_ + d;
                *(uint32_t*)(O + i0) = pack_h2(acc[mt][nt][0], acc[mt][nt][1]);
                *(uint32_t*)(O + i1) = pack_h2(acc[mt][nt][2], acc[mt][nt][3]);
            } else {
                size_t b0 = ((size_t)(bb0 * H_ + h) * D_ + d) * SP_ + ss0;
                size_t b1 = ((size_t)(bb1 * H_ + h) * D_ + d) * SP_ + ss1;
                g_Vt[b0]       = __float2half_rn(acc[mt][nt][0]);
                g_Vt[b0 + SP_] = __float2half_rn(acc[mt][nt][1]);
                g_Vt[b1]       = __float2half_rn(acc[mt][nt][2]);
                g_Vt[b1 + SP_] = __float2half_rn(acc[mt][nt][3]);
            }
        }
    }
}

// ---------------------------------------------------------------------------
// Kernel 2: attention, single-product fp16 MMA. One block per (b,h).
// smem: Q,K [192][64 fp16] pitch 144; Vt [64][192 fp16] pitch 400.
// QK^T -> bias+mask -> softmax in C-frags -> P packed to fp16 in register
// (C layout == A layout) -> PV -> scaled fp32 store.
// ---------------------------------------------------------------------------
#define QKP2  144
#define VTP2  400
#define SQ_B2  (SP_ * QKP2)               // 27648
#define SVT_B2 (D_ * VTP2)                // 25600
#define ATT_SMEM2 (2 * SQ_B2 + SVT_B2)    // 80896

__global__ __launch_bounds__(256) void attn_kernel()
{
    extern __shared__ __align__(128) char sm[];
    char* sQ = sm;
    char* sK = sm + SQ_B2;
    char* sV = sm + 2 * SQ_B2;

    const int bh = blockIdx.x;
    const int b  = bh >> 4;
    const int h  = bh & 15;
    const int tid = threadIdx.x;
    const int wid = tid >> 5;
    const int lane = tid & 31;

    {
        const uint4* qh = (const uint4*)(g_Qh + (size_t)bh * SP_ * D_);
        const uint4* kh = (const uint4*)(g_Kh + (size_t)bh * SP_ * D_);
        for (int i = tid; i < SP_ * 8; i += 256) {
            int row = i >> 3, seg = i & 7;
            *(uint4*)(sQ + row * QKP2 + seg * 16) = qh[i];
            *(uint4*)(sK + row * QKP2 + seg * 16) = kh[i];
        }
        const uint4* vh = (const uint4*)(g_Vt + (size_t)bh * D_ * SP_);
        for (int i = tid; i < D_ * 24; i += 256) {
            int row = i / 24, seg = i - row * 24;
            *(uint4*)(sV + row * VTP2 + seg * 16) = vh[i];
        }
    }
    __syncthreads();

    const uint32_t sQb = smem_u32(sQ);
    const uint32_t sKb = smem_u32(sK);
    const uint32_t sVb = smem_u32(sV);

    const uint32_t aRow = (uint32_t)(lane & 15);
    const uint32_t aOff = (uint32_t)((lane >> 4) * 16);
    const uint32_t bRow = (uint32_t)(((lane >> 4) << 3) + (lane & 7));
    const uint32_t bOff = (uint32_t)(((lane >> 3) & 1) * 16);

    const float wsc = 0.03125f / 179.0f;   // E^-0.5 / N

    for (int mtl = wid; mtl < 12; mtl += 8) {
        float acc[24][4];
#pragma unroll
        for (int t = 0; t < 24; t++)
#pragma unroll
            for (int k = 0; k < 4; k++) acc[t][k] = 0.f;

#pragma unroll
        for (int s = 0; s < 4; s++) {
            uint32_t A0, A1, A2, A3;
            uint32_t ad = sQb + (uint32_t)(mtl * 16 + aRow) * QKP2 + s * 32 + aOff;
            LDSM_X4(A0, A1, A2, A3, ad);
#pragma unroll
            for (int np = 0; np < 12; np++) {
                uint32_t B0, B1, B2, B3;
                uint32_t bd = sKb + (uint32_t)(np * 16 + bRow) * QKP2 + s * 32 + bOff;
                LDSM_X4(B0, B1, B2, B3, bd);
                MMA_F16(acc[np * 2 + 0], A0, A1, A2, A3, B0, B1);
                MMA_F16(acc[np * 2 + 1], A0, A1, A2, A3, B2, B3);
            }
        }

        const int q0 = mtl * 16 + (lane >> 2);
        const int q1 = q0 + 8;
        float m0 = -1e30f, m1 = -1e30f;
#pragma unroll
        for (int t = 0; t < 24; t++) {
            const int k0 = t * 8 + (lane & 3) * 2;
            const int k1 = k0 + 1;
            if (k0 < S_) {
                acc[t][0] *= wsc * fabsf((float)(q0 - k0));
                acc[t][2] *= wsc * fabsf((float)(q1 - k0));
            } else { acc[t][0] = -1e30f; acc[t][2] = -1e30f; }
            if (k1 < S_) {
                acc[t][1] *= wsc * fabsf((float)(q0 - k1));
                acc[t][3] *= wsc * fabsf((float)(q1 - k1));
            } else { acc[t][1] = -1e30f; acc[t][3] = -1e30f; }
            m0 = fmaxf(m0, fmaxf(acc[t][0], acc[t][1]));
            m1 = fmaxf(m1, fmaxf(acc[t][2], acc[t][3]));
        }
        m0 = fmaxf(m0, __shfl_xor_sync(0xffffffffu, m0, 1));
        m0 = fmaxf(m0, __shfl_xor_sync(0xffffffffu, m0, 2));
        m1 = fmaxf(m1, __shfl_xor_sync(0xffffffffu, m1, 1));
        m1 = fmaxf(m1, __shfl_xor_sync(0xffffffffu, m1, 2));

        float s0 = 0.f, s1 = 0.f;
#pragma unroll
        for (int t = 0; t < 24; t++) {
            acc[t][0] = __expf(acc[t][0] - m0);
            acc[t][1] = __expf(acc[t][1] - m0);
            acc[t][2] = __expf(acc[t][2] - m1);
            acc[t][3] = __expf(acc[t][3] - m1);
            s0 += acc[t][0] + acc[t][1];
            s1 += acc[t][2] + acc[t][3];
        }
        s0 += __shfl_xor_sync(0xffffffffu, s0, 1);
        s0 += __shfl_xor_sync(0xffffffffu, s0, 2);
        s1 += __shfl_xor_sync(0xffffffffu, s1, 1);
        s1 += __shfl_xor_sync(0xffffffffu, s1, 2);
        const float inv0 = 1.0f / s0;
        const float inv1 = 1.0f / s1;

        float o[8][4];
#pragma unroll
        for (int nt = 0; nt < 8; nt++)
#pragma unroll
            for (int k = 0; k < 4; k++) o[nt][k] = 0.f;

#pragma unroll
        for (int s = 0; s < 12; s++) {
            const uint32_t a0 = pack_h2(acc[2*s][0],   acc[2*s][1]);
            const uint32_t a1 = pack_h2(acc[2*s][2],   acc[2*s][3]);
            const uint32_t a2 = pack_h2(acc[2*s+1][0], acc[2*s+1][1]);
            const uint32_t a3 = pack_h2(acc[2*s+1][2], acc[2*s+1][3]);
#pragma unroll
            for (int np = 0; np < 4; np++) {
                uint32_t B0, B1, B2, B3;
                uint32_t bd = sVb + (uint32_t)(np * 16 + bRow) * VTP2 + s * 32 + bOff;
                LDSM_X4(B0, B1, B2, B3, bd);
                MMA_F16(o[np * 2 + 0], a0, a1, a2, a3, B0, B1);
                MMA_F16(o[np * 2 + 1], a0, a1, a2, a3, B2, B3);
            }
        }

#pragma unroll
        for (int nt = 0; nt < 8; nt++) {
            const int d = nt * 8 + (lane & 3) * 2;
            if (q0 < S_) {
                float* p = g_att + ((size_t)(b * S_ + q0)) * E_ + h * 64 + d;
                *(float2*)p = make_float2(o[nt][0] * inv0, o[nt][1] * inv0);
            }
            if (q1 < S_) {
                float* p = g_att + ((size_t)(b * S_ + q1)) * E_ + h * 64 + d;
                *(float2*)p = make_float2(o[nt][2] * inv1, o[nt][3] * inv1);
            }
        }
    }
}

// ---------------------------------------------------------------------------
// Kernel 3: LayerNorm over last dim (1024). One block per row.
// ---------------------------------------------------------------------------
__global__ __launch_bounds__(256) void ln_kernel(
    const float* __restrict__ gamma,
    const float* __restrict__ beta,
    float* __restrict__ out)
{
    const int row = blockIdx.x;
    const int tid = threadIdx.x;
    const float4 v = ((const float4*)(g_att + (size_t)row * E_))[tid];

    float s  = v.x + v.y + v.z + v.w;
    float s2 = v.x * v.x + v.y * v.y + v.z * v.z + v.w * v.w;
#pragma unroll
    for (int o = 16; o > 0; o >>= 1) {
        s  += __shfl_xor_sync(0xffffffffu, s, o);
        s2 += __shfl_xor_sync(0xffffffffu, s2, o);
    }
    __shared__ float red[2][8];
    const int wid = tid >> 5, lane = tid & 31;
    if (lane == 0) { red[0][wid] = s; red[1][wid] = s2; }
    __syncthreads();
    float fs = 0.f, fs2 = 0.f;
#pragma unroll
    for (int w = 0; w < 8; w++) { fs += red[0][w]; fs2 += red[1][w]; }

    const float mu  = fs * (1.0f / E_);
    const float var = fs2 * (1.0f / E_) - mu * mu;
    const float inv = rsqrtf(var + 1e-5f);

    const float4 g  = ((const float4*)gamma)[tid];
    const float4 bt = ((const float4*)beta)[tid];
    float4 r;
    r.x = (v.x - mu) * inv * g.x + bt.x;
    r.y = (v.y - mu) * inv * g.y + bt.y;
    r.z = (v.z - mu) * inv * g.z + bt.z;
    r.w = (v.w - mu) * inv * g.w + bt.w;
    ((float4*)out)[(size_t)row * 256 + tid] = r;
}

// ---------------------------------------------------------------------------
extern "C" void kernel_launch(void* const* d_in, const int* in_sizes, int n_in,
                              void* d_out, int out_size)
{
    const float* x     = (const float*)d_in[0];
    const float* Wq    = (const float*)d_in[1];
    const float* Wk    = (const float*)d_in[2];
    const float* Wv    = (const float*)d_in[3];
    const float* gamma = (const float*)d_in[4];
    const float* beta  = (const float*)d_in[5];
    float* out = (float*)d_out;

    const int gemm_smem = 4 * STAGE_F;      // 81920
    cudaFuncSetAttribute(qkv_gemm_f16, cudaFuncAttributeMaxDynamicSharedMemorySize, gemm_smem);
    cudaFuncSetAttribute(attn_kernel, cudaFuncAttributeMaxDynamicSharedMemorySize, ATT_SMEM2);

    cvt_fp16<<<dim3((BS_ * E_ / 4 + 255) / 256, 4), 256>>>(x, Wq, Wk, Wv);
    qkv_gemm_f16<<<dim3(BS_ / 128, E_ / 128, 3), 128, gemm_smem>>>();
    attn_kernel<<<BH_, 256, ATT_SMEM2>>>();
    ln_kernel<<<BS_, 256>>>(gamma, beta, out);
}

// round 6
// speedup vs baseline: 6.9652x; 1.0267x over previous
#include <cuda_runtime.h>
#include <cuda_fp16.h>
#include <cstdint>
#include <math.h>

#define B_   128
#define S_   179
#define E_   1024
#define H_   16
#define D_   64
#define BS_  (B_ * S_)          // 22912
#define BH_  (B_ * H_)          // 2048
#define SP_  192                // padded sequence (12 x 16)
#define EE_  (E_ * E_)

// fp16 copies of inputs: [ x (BS_*E_) | Wq | Wk | Wv ]
__device__ __half g_fp16[(size_t)BS_ * E_ + 3 * EE_];
// projection outputs (fp16). Pad rows [179,192) never written -> stay zero.
__device__ __half g_Qh[BH_ * SP_ * D_];
__device__ __half g_Kh[BH_ * SP_ * D_];
__device__ __half g_Vt[BH_ * D_ * SP_];   // transposed: [bh][d][s]
__device__ float g_att[(size_t)BS_ * E_];

// ---------------------------------------------------------------------------
// helpers
// ---------------------------------------------------------------------------
__device__ __forceinline__ uint32_t smem_u32(const void* p) {
    uint32_t a;
    asm("{ .reg .u64 t; cvta.to.shared.u64 t, %1; cvt.u32.u64 %0, t; }" : "=r"(a) : "l"(p));
    return a;
}
__device__ __forceinline__ uint32_t pack_h2(float x, float y) {
    __half2 h = __floats2half2_rn(x, y);
    return *reinterpret_cast<uint32_t*>(&h);
}

#define LDSM_X4(r0, r1, r2, r3, addr)                                          \
    asm volatile("ldmatrix.sync.aligned.m8n8.x4.shared.b16 {%0,%1,%2,%3}, [%4];" \
                 : "=r"(r0), "=r"(r1), "=r"(r2), "=r"(r3) : "r"(addr))

#define MMA_F16(c, a0, a1, a2, a3, b0, b1)                                     \
    asm volatile("mma.sync.aligned.m16n8k16.row.col.f32.f16.f16.f32 "          \
        "{%0,%1,%2,%3}, {%4,%5,%6,%7}, {%8,%9}, {%0,%1,%2,%3};"                \
        : "+f"((c)[0]), "+f"((c)[1]), "+f"((c)[2]), "+f"((c)[3])               \
        : "r"(a0), "r"(a1), "r"(a2), "r"(a3), "r"(b0), "r"(b1))

#define CP16(dst, src)                                                         \
    asm volatile("cp.async.cg.shared.global [%0], [%1], 16;" :: "r"(dst), "l"(src) : "memory")
#define CP_COMMIT()  asm volatile("cp.async.commit_group;" ::: "memory")
#define CP_WAIT1()   asm volatile("cp.async.wait_group 1;" ::: "memory")

// ---------------------------------------------------------------------------
// Kernel 0: fp32 -> fp16 pre-convert of x and the three weight matrices.
// ---------------------------------------------------------------------------
__global__ __launch_bounds__(256) void cvt_fp16(
    const float* __restrict__ x,  const float* __restrict__ Wq,
    const float* __restrict__ Wk, const float* __restrict__ Wv)
{
    const int z = blockIdx.y;
    const float* src = (z == 0) ? x : ((z == 1) ? Wq : ((z == 2) ? Wk : Wv));
    const size_t cnt = (z == 0) ? (size_t)BS_ * E_ : (size_t)EE_;
    const size_t off = (z == 0) ? 0 : (size_t)BS_ * E_ + (size_t)(z - 1) * EE_;
    const size_t i = ((size_t)blockIdx.x * 256 + threadIdx.x) * 4;
    if (i < cnt) {
        float4 v = *(const float4*)(src + i);
        *(uint2*)(g_fp16 + off + i) = make_uint2(pack_h2(v.x, v.y), pack_h2(v.z, v.w));
    }
}

// ---------------------------------------------------------------------------
// Kernel 1: QKV projection, fp16 MMA.  C = A @ W^T.
// CTA 128x128, 4 warps (warp tile 64x64), KC=32, 3-stage cp.async pipeline,
// 3 CTAs/SM. Pipeline order per iter: wait_group(1) -> sync -> issue c+2
// (safe: overwrites buf of c-1, and all warps passed sync after computing
// c-1) -> compute c.
// ---------------------------------------------------------------------------
#define KCH     32
#define NCH     (E_ / KCH)      // 32
#define PG      80
#define TILE_F  (128 * PG)      // 10240 per operand tile
#define STAGE_F (2 * TILE_F)    // 20480 (A+B)
#define NSTG    3

__global__ __launch_bounds__(128, 3) void qkv_gemm_f16()
{
    extern __shared__ __align__(128) char sb[];
    const int z = blockIdx.z;
    const int bm = blockIdx.x * 128;
    const int bn = blockIdx.y * 128;
    const int tid = threadIdx.x;
    const int wid = tid >> 5;
    const int lane = tid & 31;

    const uint32_t sbase = smem_u32(sb);
    const int warp_m = (wid >> 1) * 64;
    const int warp_n = (wid & 1) * 64;

    const __half* gA = g_fp16 + (size_t)(bm + tid) * E_;
    const __half* gB = g_fp16 + (size_t)BS_ * E_ + (size_t)z * EE_ + (size_t)(bn + tid) * E_;
    const uint32_t dA0 = sbase + (uint32_t)tid * PG;

    const uint32_t aRow = (uint32_t)(lane & 15);
    const uint32_t aOff = (uint32_t)((lane >> 4) * 16);
    const uint32_t bRow = (uint32_t)(((lane >> 4) << 3) + (lane & 7));
    const uint32_t bOff = (uint32_t)(((lane >> 3) & 1) * 16);

    float acc[4][8][4];
#pragma unroll
    for (int i = 0; i < 4; i++)
#pragma unroll
        for (int j = 0; j < 8; j++)
#pragma unroll
            for (int k = 0; k < 4; k++) acc[i][j][k] = 0.f;

    // prologue: chunks 0,1 -> stages 0,1
#pragma unroll
    for (int p = 0; p < 2; p++) {
        uint32_t dA = dA0 + (uint32_t)p * STAGE_F;
        uint32_t dB = dA + TILE_F;
        const __half* sA = gA + p * KCH;
        const __half* sB = gB + p * KCH;
#pragma unroll
        for (int j = 0; j < 4; j++) {
            CP16(dA + j * 16, sA + j * 8);
            CP16(dB + j * 16, sB + j * 8);
        }
        CP_COMMIT();
    }

    int buf = 0;           // stage of chunk c
    int nbuf = 2;          // stage for chunk c+2
    for (int c = 0; c < NCH; c++) {
        CP_WAIT1();        // committed 0..c+1, pending<=1 -> chunk c resident
        __syncthreads();   // data-ready for all warps + all done computing c-1

        if (c + 2 < NCH) {
            uint32_t dA = dA0 + (uint32_t)nbuf * STAGE_F;
            uint32_t dB = dA + TILE_F;
            const __half* sA = gA + (c + 2) * KCH;
            const __half* sB = gB + (c + 2) * KCH;
#pragma unroll
            for (int j = 0; j < 4; j++) {
                CP16(dA + j * 16, sA + j * 8);
                CP16(dB + j * 16, sB + j * 8);
            }
        }
        CP_COMMIT();

        const uint32_t stA = sbase + (uint32_t)buf * STAGE_F;
        const uint32_t stB = stA + TILE_F;
#pragma unroll
        for (int s = 0; s < 2; s++) {
            uint32_t Af[4][4];
#pragma unroll
            for (int mt = 0; mt < 4; mt++) {
                uint32_t ad = stA + (uint32_t)(warp_m + mt * 16 + aRow) * PG + s * 32 + aOff;
                LDSM_X4(Af[mt][0], Af[mt][1], Af[mt][2], Af[mt][3], ad);
            }
#pragma unroll
            for (int np = 0; np < 4; np++) {
                uint32_t B0, B1, B2, B3;
                uint32_t bd = stB + (uint32_t)(warp_n + np * 16 + bRow) * PG + s * 32 + bOff;
                LDSM_X4(B0, B1, B2, B3, bd);
#pragma unroll
                for (int mt = 0; mt < 4; mt++) {
                    MMA_F16(acc[mt][np * 2 + 0], Af[mt][0], Af[mt][1], Af[mt][2], Af[mt][3], B0, B1);
                    MMA_F16(acc[mt][np * 2 + 1], Af[mt][0], Af[mt][1], Af[mt][2], Af[mt][3], B2, B3);
                }
            }
        }
        buf  = (buf  + 1 == NSTG) ? 0 : buf  + 1;
        nbuf = (nbuf + 1 == NSTG) ? 0 : nbuf + 1;
    }

    // epilogue: fp16 stores
#pragma unroll
    for (int mt = 0; mt < 4; mt++) {
        const int r0 = bm + warp_m + mt * 16 + (lane >> 2);
        const int r1 = r0 + 8;
        const int bb0 = r0 / S_, ss0 = r0 - bb0 * S_;
        const int bb1 = r1 / S_, ss1 = r1 - bb1 * S_;
#pragma unroll
        for (int nt = 0; nt < 8; nt++) {
            const int n = bn + warp_n + nt * 8 + ((lane & 3) * 2);
            const int h = n >> 6;
            const int d = n & 63;
            if (z < 2) {
                __half* O = (z == 0) ? g_Qh : g_Kh;
                size_t i0 = ((size_t)(bb0 * H_ + h) * SP_ + ss0) * D_ + d;
                size_t i1 = ((size_t)(bb1 * H_ + h) * SP_ + ss1) * D_ + d;
                *(uint32_t*)(O + i0) = pack_h2(acc[mt][nt][0], acc[mt][nt][1]);
                *(uint32_t*)(O + i1) = pack_h2(acc[mt][nt][2], acc[mt][nt][3]);
            } else {
                size_t b0 = ((size_t)(bb0 * H_ + h) * D_ + d) * SP_ + ss0;
                size_t b1 = ((size_t)(bb1 * H_ + h) * D_ + d) * SP_ + ss1;
                g_Vt[b0]       = __float2half_rn(acc[mt][nt][0]);
                g_Vt[b0 + SP_] = __float2half_rn(acc[mt][nt][1]);
                g_Vt[b1]       = __float2half_rn(acc[mt][nt][2]);
                g_Vt[b1 + SP_] = __float2half_rn(acc[mt][nt][3]);
            }
        }
    }
}

// ---------------------------------------------------------------------------
// Kernel 2: attention, fp16 MMA. One block per (b,h), 384 threads = 12 warps,
// one 16-query m-tile per warp (balanced; was 12 tiles over 8 warps).
// ---------------------------------------------------------------------------
#define QKP2  144
#define VTP2  400
#define SQ_B2  (SP_ * QKP2)               // 27648
#define SVT_B2 (D_ * VTP2)                // 25600
#define ATT_SMEM2 (2 * SQ_B2 + SVT_B2)    // 80896

__global__ __launch_bounds__(384) void attn_kernel()
{
    extern __shared__ __align__(128) char sm[];
    char* sQ = sm;
    char* sK = sm + SQ_B2;
    char* sV = sm + 2 * SQ_B2;

    const int bh = blockIdx.x;
    const int b  = bh >> 4;
    const int h  = bh & 15;
    const int tid = threadIdx.x;
    const int wid = tid >> 5;      // 0..11
    const int lane = tid & 31;

    {
        const uint4* qh = (const uint4*)(g_Qh + (size_t)bh * SP_ * D_);
        const uint4* kh = (const uint4*)(g_Kh + (size_t)bh * SP_ * D_);
        for (int i = tid; i < SP_ * 8; i += 384) {
            int row = i >> 3, seg = i & 7;
            *(uint4*)(sQ + row * QKP2 + seg * 16) = qh[i];
            *(uint4*)(sK + row * QKP2 + seg * 16) = kh[i];
        }
        const uint4* vh = (const uint4*)(g_Vt + (size_t)bh * D_ * SP_);
        for (int i = tid; i < D_ * 24; i += 384) {
            int row = i / 24, seg = i - row * 24;
            *(uint4*)(sV + row * VTP2 + seg * 16) = vh[i];
        }
    }
    __syncthreads();

    const uint32_t sQb = smem_u32(sQ);
    const uint32_t sKb = smem_u32(sK);
    const uint32_t sVb = smem_u32(sV);

    const uint32_t aRow = (uint32_t)(lane & 15);
    const uint32_t aOff = (uint32_t)((lane >> 4) * 16);
    const uint32_t bRow = (uint32_t)(((lane >> 4) << 3) + (lane & 7));
    const uint32_t bOff = (uint32_t)(((lane >> 3) & 1) * 16);

    const float wsc = 0.03125f / 179.0f;   // E^-0.5 / N
    const int mtl = wid;                   // one m-tile per warp

    float acc[24][4];
#pragma unroll
    for (int t = 0; t < 24; t++)
#pragma unroll
        for (int k = 0; k < 4; k++) acc[t][k] = 0.f;

#pragma unroll
    for (int s = 0; s < 4; s++) {
        uint32_t A0, A1, A2, A3;
        uint32_t ad = sQb + (uint32_t)(mtl * 16 + aRow) * QKP2 + s * 32 + aOff;
        LDSM_X4(A0, A1, A2, A3, ad);
#pragma unroll
        for (int np = 0; np < 12; np++) {
            uint32_t B0, B1, B2, B3;
            uint32_t bd = sKb + (uint32_t)(np * 16 + bRow) * QKP2 + s * 32 + bOff;
            LDSM_X4(B0, B1, B2, B3, bd);
            MMA_F16(acc[np * 2 + 0], A0, A1, A2, A3, B0, B1);
            MMA_F16(acc[np * 2 + 1], A0, A1, A2, A3, B2, B3);
        }
    }

    const int q0 = mtl * 16 + (lane >> 2);
    const int q1 = q0 + 8;
    float m0 = -1e30f, m1 = -1e30f;
#pragma unroll
    for (int t = 0; t < 24; t++) {
        const int k0 = t * 8 + (lane & 3) * 2;
        const int k1 = k0 + 1;
        if (k0 < S_) {
            acc[t][0] *= wsc * fabsf((float)(q0 - k0));
            acc[t][2] *= wsc * fabsf((float)(q1 - k0));
        } else { acc[t][0] = -1e30f; acc[t][2] = -1e30f; }
        if (k1 < S_) {
            acc[t][1] *= wsc * fabsf((float)(q0 - k1));
            acc[t][3] *= wsc * fabsf((float)(q1 - k1));
        } else { acc[t][1] = -1e30f; acc[t][3] = -1e30f; }
        m0 = fmaxf(m0, fmaxf(acc[t][0], acc[t][1]));
        m1 = fmaxf(m1, fmaxf(acc[t][2], acc[t][3]));
    }
    m0 = fmaxf(m0, __shfl_xor_sync(0xffffffffu, m0, 1));
    m0 = fmaxf(m0, __shfl_xor_sync(0xffffffffu, m0, 2));
    m1 = fmaxf(m1, __shfl_xor_sync(0xffffffffu, m1, 1));
    m1 = fmaxf(m1, __shfl_xor_sync(0xffffffffu, m1, 2));

    float s0 = 0.f, s1 = 0.f;
#pragma unroll
    for (int t = 0; t < 24; t++) {
        acc[t][0] = __expf(acc[t][0] - m0);
        acc[t][1] = __expf(acc[t][1] - m0);
        acc[t][2] = __expf(acc[t][2] - m1);
        acc[t][3] = __expf(acc[t][3] - m1);
        s0 += acc[t][0] + acc[t][1];
        s1 += acc[t][2] + acc[t][3];
    }
    s0 += __shfl_xor_sync(0xffffffffu, s0, 1);
    s0 += __shfl_xor_sync(0xffffffffu, s0, 2);
    s1 += __shfl_xor_sync(0xffffffffu, s1, 1);
    s1 += __shfl_xor_sync(0xffffffffu, s1, 2);
    const float inv0 = 1.0f / s0;
    const float inv1 = 1.0f / s1;

    float o[8][4];
#pragma unroll
    for (int nt = 0; nt < 8; nt++)
#pragma unroll
        for (int k = 0; k < 4; k++) o[nt][k] = 0.f;

#pragma unroll
    for (int s = 0; s < 12; s++) {
        const uint32_t a0 = pack_h2(acc[2*s][0],   acc[2*s][1]);
        const uint32_t a1 = pack_h2(acc[2*s][2],   acc[2*s][3]);
        const uint32_t a2 = pack_h2(acc[2*s+1][0], acc[2*s+1][1]);
        const uint32_t a3 = pack_h2(acc[2*s+1][2], acc[2*s+1][3]);
#pragma unroll
        for (int np = 0; np < 4; np++) {
            uint32_t B0, B1, B2, B3;
            uint32_t bd = sVb + (uint32_t)(np * 16 + bRow) * VTP2 + s * 32 + bOff;
            LDSM_X4(B0, B1, B2, B3, bd);
            MMA_F16(o[np * 2 + 0], a0, a1, a2, a3, B0, B1);
            MMA_F16(o[np * 2 + 1], a0, a1, a2, a3, B2, B3);
        }
    }

#pragma unroll
    for (int nt = 0; nt < 8; nt++) {
        const int d = nt * 8 + (lane & 3) * 2;
        if (q0 < S_) {
            float* p = g_att + ((size_t)(b * S_ + q0)) * E_ + h * 64 + d;
            *(float2*)p = make_float2(o[nt][0] * inv0, o[nt][1] * inv0);
        }
        if (q1 < S_) {
            float* p = g_att + ((size_t)(b * S_ + q1)) * E_ + h * 64 + d;
            *(float2*)p = make_float2(o[nt][2] * inv1, o[nt][3] * inv1);
        }
    }
}

// ---------------------------------------------------------------------------
// Kernel 3: LayerNorm over last dim (1024). One block per row.
// ---------------------------------------------------------------------------
__global__ __launch_bounds__(256) void ln_kernel(
    const float* __restrict__ gamma,
    const float* __restrict__ beta,
    float* __restrict__ out)
{
    const int row = blockIdx.x;
    const int tid = threadIdx.x;
    const float4 v = ((const float4*)(g_att + (size_t)row * E_))[tid];

    float s  = v.x + v.y + v.z + v.w;
    float s2 = v.x * v.x + v.y * v.y + v.z * v.z + v.w * v.w;
#pragma unroll
    for (int o = 16; o > 0; o >>= 1) {
        s  += __shfl_xor_sync(0xffffffffu, s, o);
        s2 += __shfl_xor_sync(0xffffffffu, s2, o);
    }
    __shared__ float red[2][8];
    const int wid = tid >> 5, lane = tid & 31;
    if (lane == 0) { red[0][wid] = s; red[1][wid] = s2; }
    __syncthreads();
    float fs = 0.f, fs2 = 0.f;
#pragma unroll
    for (int w = 0; w < 8; w++) { fs += red[0][w]; fs2 += red[1][w]; }

    const float mu  = fs * (1.0f / E_);
    const float var = fs2 * (1.0f / E_) - mu * mu;
    const float inv = rsqrtf(var + 1e-5f);

    const float4 g  = ((const float4*)gamma)[tid];
    const float4 bt = ((const float4*)beta)[tid];
    float4 r;
    r.x = (v.x - mu) * inv * g.x + bt.x;
    r.y = (v.y - mu) * inv * g.y + bt.y;
    r.z = (v.z - mu) * inv * g.z + bt.z;
    r.w = (v.w - mu) * inv * g.w + bt.w;
    ((float4*)out)[(size_t)row * 256 + tid] = r;
}

// ---------------------------------------------------------------------------
extern "C" void kernel_launch(void* const* d_in, const int* in_sizes, int n_in,
                              void* d_out, int out_size)
{
    const float* x     = (const float*)d_in[0];
    const float* Wq    = (const float*)d_in[1];
    const float* Wk    = (const float*)d_in[2];
    const float* Wv    = (const float*)d_in[3];
    const float* gamma = (const float*)d_in[4];
    const float* beta  = (const float*)d_in[5];
    float* out = (float*)d_out;

    const int gemm_smem = NSTG * STAGE_F;   // 61440
    cudaFuncSetAttribute(qkv_gemm_f16, cudaFuncAttributeMaxDynamicSharedMemorySize, gemm_smem);
    cudaFuncSetAttribute(attn_kernel, cudaFuncAttributeMaxDynamicSharedMemorySize, ATT_SMEM2);

    cvt_fp16<<<dim3((BS_ * E_ / 4 + 255) / 256, 4), 256>>>(x, Wq, Wk, Wv);
    qkv_gemm_f16<<<dim3(BS_ / 128, E_ / 128, 3), 128, gemm_smem>>>();
    attn_kernel<<<BH_, 384, ATT_SMEM2>>>();
    ln_kernel<<<BS_, 256>>>(gamma, beta, out);
}